// round 5
// baseline (speedup 1.0000x reference)
#include <cuda_runtime.h>
#include <cstdint>

#define TPC 8   // tokens per CTA -> per-thread MLP of 8 on the weight loads

// One CTA per TPC tokens, 256 threads. Thread t owns 16-byte vector t of each
// token's 1024-element row. TPC independent 16B weight loads in flight per
// thread before any use -> deep MLP to cover ~600cyc DRAM latency.
//
// Index dtype (int64 vs int32) detected inline: lane L probes high word of
// entry L of x under the int64 interpretation (same 256B region for every
// CTA -> L2 hot). int64 => all high words 0 (indices < 128000); int32 =>
// those words are random indices, P(all 32 == 0) ~ (1/128000)^32 ~ 0.
// Indices themselves are loaded only by lanes 0..TPC-1 (both interpretations,
// independent of the probe) and broadcast via shfl — 2 index LDGs per thread
// instead of 2*TPC.
__global__ __launch_bounds__(256)
void int4_embedding_kernel(const int* __restrict__ x32,
                           const int4* __restrict__ weight,    // [V, 256] int4 vecs
                           const float* __restrict__ scale,    // [V, 32]
                           const int* __restrict__ zero_point, // [V, 32]
                           float4* __restrict__ out,           // [T, 256]
                           int n_tokens)
{
    const int t = threadIdx.x;                          // 0..255
    const int lane = t & 31;
    const long long base = (long long)blockIdx.x * TPC;
    const int rem = (int)(n_tokens - base);
    const int nt = rem < TPC ? rem : TPC;

    // --- independent loads, all issued together ---------------------------
    const int hi_probe = (lane < n_tokens) ? __ldg(x32 + 2 * lane + 1) : 0;

    int my64 = 0, my32 = 0;
    if (lane < nt) {                                    // TPC <= 32
        my64 = __ldg(x32 + 2 * (base + lane));          // int64 low word
        my32 = __ldg(x32 + (base + lane));              // int32 value
    }

    // --- resolve dtype + broadcast indices (no extra round-trips) ---------
    const bool is64 = (__ballot_sync(0xFFFFFFFFu, hi_probe != 0) == 0u);
    const int mysel = is64 ? my64 : my32;

    int v[TPC];
    #pragma unroll
    for (int i = 0; i < TPC; ++i)
        v[i] = __shfl_sync(0xFFFFFFFFu, mysel, i);

    // --- weight loads: TPC independent 16B loads in flight ----------------
    int4 w[TPC];
    #pragma unroll
    for (int i = 0; i < TPC; ++i)
        w[i] = __ldg(weight + (size_t)(unsigned)v[i] * 256 + t);

    const int g = t >> 3;                                // group = (4t)/32
    float s[TPC], z[TPC];
    #pragma unroll
    for (int i = 0; i < TPC; ++i) {
        const size_t srow = (size_t)(unsigned)v[i] * 32 + g;
        s[i] = __ldg(scale + srow);
        z[i] = (float)__ldg(zero_point + srow);
    }

    #pragma unroll
    for (int i = 0; i < TPC; ++i) {
        float4 o;
        o.x = ((float)w[i].x - z[i]) * s[i];
        o.y = ((float)w[i].y - z[i]) * s[i];
        o.z = ((float)w[i].z - z[i]) * s[i];
        o.w = ((float)w[i].w - z[i]) * s[i];
        if (i < nt) {
            // Streaming store: output is write-once — keep it out of L2 so L2
            // capacity goes to weight-row reuse (duplicate indices).
            __stcs(out + (size_t)(base + i) * 256 + t, o);
        }
    }
}

extern "C" void kernel_launch(void* const* d_in, const int* in_sizes, int n_in,
                              void* d_out, int out_size) {
    const int*   x      = (const int*)d_in[0];        // [32, 2048] int64 (or int32)
    const int4*  weight = (const int4*)d_in[1];       // [128000, 1024] int32
    const float* scale  = (const float*)d_in[2];      // [128000, 32] fp32
    const int*   zp     = (const int*)d_in[3];        // [128000, 32] int32
    float4*      out    = (float4*)d_out;             // [32, 2048, 1024] fp32

    const int n_tokens = in_sizes[0];                 // 65536

    const int grid = (n_tokens + TPC - 1) / TPC;
    int4_embedding_kernel<<<grid, 256>>>(x, weight, scale, zp, out, n_tokens);
}

// round 6
// speedup vs baseline: 1.0234x; 1.0234x over previous
#include <cuda_runtime.h>
#include <cstdint>

#define TPC 8   // tokens per CTA -> per-thread MLP of 8 on the weight loads

// One CTA per TPC tokens, 256 threads. Thread t owns 16-byte vector t of each
// token's 1024-element row. __launch_bounds__(256, 3) grants ~84 regs/thread
// so all TPC int4 weight loads (32 regs) stay live simultaneously -> true
// MLP=8 (round-5's default-regalloc build collapsed to 32 regs and serialized
// the loads, never testing the hypothesis).
//
// Index dtype (int64 vs int32) detected inline: lane L probes high word of
// entry L of x under the int64 interpretation (same 256B region for every
// CTA -> L2 hot). int64 => all high words 0 (indices < 128000); int32 =>
// those words are random indices, P(all 32 == 0) ~ (1/128000)^32 ~ 0.
// Indices loaded only by lanes 0..TPC-1 (both interpretations, independent of
// the probe) and broadcast via shfl.
__global__ __launch_bounds__(256, 3)
void int4_embedding_kernel(const int* __restrict__ x32,
                           const int4* __restrict__ weight,    // [V, 256] int4 vecs
                           const float* __restrict__ scale,    // [V, 32]
                           const int* __restrict__ zero_point, // [V, 32]
                           float4* __restrict__ out,           // [T, 256]
                           int n_tokens)
{
    const int t = threadIdx.x;                          // 0..255
    const int lane = t & 31;
    const long long base = (long long)blockIdx.x * TPC;
    const int rem = (int)(n_tokens - base);
    const int nt = rem < TPC ? rem : TPC;

    // --- independent loads, all issued together ---------------------------
    const int hi_probe = (lane < n_tokens) ? __ldg(x32 + 2 * lane + 1) : 0;

    int my64 = 0, my32 = 0;
    if (lane < nt) {                                    // TPC <= 32
        my64 = __ldg(x32 + 2 * (base + lane));          // int64 low word
        my32 = __ldg(x32 + (base + lane));              // int32 value
    }

    // --- resolve dtype + broadcast indices (no extra round-trips) ---------
    const bool is64 = (__ballot_sync(0xFFFFFFFFu, hi_probe != 0) == 0u);
    const int mysel = is64 ? my64 : my32;

    int v[TPC];
    #pragma unroll
    for (int i = 0; i < TPC; ++i)
        v[i] = __shfl_sync(0xFFFFFFFFu, mysel, i);

    // --- weight loads: TPC independent 16B loads, all in flight -----------
    int4 w[TPC];
    #pragma unroll
    for (int i = 0; i < TPC; ++i)
        w[i] = __ldg(weight + (size_t)(unsigned)v[i] * 256 + t);

    const int g = t >> 3;                                // group = (4t)/32
    float s[TPC], z[TPC];
    #pragma unroll
    for (int i = 0; i < TPC; ++i) {
        const size_t srow = (size_t)(unsigned)v[i] * 32 + g;
        s[i] = __ldg(scale + srow);
        z[i] = (float)__ldg(zero_point + srow);
    }

    #pragma unroll
    for (int i = 0; i < TPC; ++i) {
        float4 o;
        o.x = ((float)w[i].x - z[i]) * s[i];
        o.y = ((float)w[i].y - z[i]) * s[i];
        o.z = ((float)w[i].z - z[i]) * s[i];
        o.w = ((float)w[i].w - z[i]) * s[i];
        if (i < nt) {
            // Streaming store: output is write-once — keep it out of L2 so L2
            // capacity goes to weight-row reuse (duplicate indices).
            __stcs(out + (size_t)(base + i) * 256 + t, o);
        }
    }
}

extern "C" void kernel_launch(void* const* d_in, const int* in_sizes, int n_in,
                              void* d_out, int out_size) {
    const int*   x      = (const int*)d_in[0];        // [32, 2048] int64 (or int32)
    const int4*  weight = (const int4*)d_in[1];       // [128000, 1024] int32
    const float* scale  = (const float*)d_in[2];      // [128000, 32] fp32
    const int*   zp     = (const int*)d_in[3];        // [128000, 32] int32
    float4*      out    = (float4*)d_out;             // [32, 2048, 1024] fp32

    const int n_tokens = in_sizes[0];                 // 65536

    const int grid = (n_tokens + TPC - 1) / TPC;
    int4_embedding_kernel<<<grid, 256>>>(x, weight, scale, zp, out, n_tokens);
}